// round 5
// baseline (speedup 1.0000x reference)
#include <cuda_runtime.h>
#include <cuda_fp16.h>
#include <cstdint>

#define NMAX 50000
#define EMAX 800000
#define ETMAX (EMAX + NMAX)
#define NBLK_MAX ((NMAX + 255) / 256)

// ---------------- scratch (device globals: allocation-free) ----------------
__device__ __half g_h1h[NMAX * 128];   // layer1 pre-act features [N,4,32] (fp16)
__device__ float g_as1[NMAX * 4];      // alpha_src per (node, head)
__device__ float g_ad1[NMAX * 4];      // alpha_dst per (node, head)
__device__ float g_h2[NMAX * 2];       // layer2 features
__device__ float g_as2[NMAX];
__device__ float g_ad2[NMAX];
__device__ int   g_cnt[NMAX];          // in-degree (incl. self loop)
__device__ int   g_row[NMAX + 1];      // CSR row starts (by dst)
__device__ int   g_ofs[NMAX];          // scatter cursors
__device__ int   g_srcs[ETMAX];        // CSR column (src) indices
__device__ int   g_blk[NBLK_MAX];      // per-block count sums
__device__ int   g_blkpre[NBLK_MAX];   // exclusive prefix of block sums

__device__ __forceinline__ float lrelu(float v) { return v > 0.f ? v : 0.2f * v; }

// ---------------- CSR build ------------------------------------------------
__global__ void k_init(int n) {
    int i = blockIdx.x * blockDim.x + threadIdx.x;
    if (i < n) g_cnt[i] = 1;            // the self loop
}
__global__ void k_hist(const int* __restrict__ ei, int Eo) {
    int e = blockIdx.x * blockDim.x + threadIdx.x;
    if (e < Eo) atomicAdd(g_cnt + ei[Eo + e], 1);
}
// pass 1: per-block sums of g_cnt
__global__ void k_scan1(int n) {
    __shared__ int sh[256];
    int i = blockIdx.x * 256 + threadIdx.x;
    sh[threadIdx.x] = (i < n) ? g_cnt[i] : 0;
    __syncthreads();
    #pragma unroll
    for (int off = 128; off; off >>= 1) {
        if (threadIdx.x < off) sh[threadIdx.x] += sh[threadIdx.x + off];
        __syncthreads();
    }
    if (threadIdx.x == 0) g_blk[blockIdx.x] = sh[0];
}
// pass 2: single-block shuffle scan of the spine (nblk <= 512)
__global__ void k_scan2(int nblk) {
    __shared__ int warpsum[16];
    int t = threadIdx.x, lane = t & 31, wp = t >> 5;
    int v = (t < nblk) ? g_blk[t] : 0;
    // inclusive scan within warp
    int s = v;
    #pragma unroll
    for (int off = 1; off < 32; off <<= 1) {
        int u = __shfl_up_sync(0xffffffffu, s, off);
        if (lane >= off) s += u;
    }
    if (lane == 31) warpsum[wp] = s;
    __syncthreads();
    if (wp == 0) {
        int ws = (lane < 16) ? warpsum[lane] : 0;
        #pragma unroll
        for (int off = 1; off < 16; off <<= 1) {
            int u = __shfl_up_sync(0xffffffffu, ws, off);
            if (lane >= off) ws += u;
        }
        if (lane < 16) warpsum[lane] = ws;
    }
    __syncthreads();
    int base = wp ? warpsum[wp - 1] : 0;
    if (t < nblk) g_blkpre[t] = base + s - v;   // exclusive
}
// pass 3: per-block exclusive scan + spine offset -> row starts / cursors
__global__ void k_scan3(int n) {
    __shared__ int warpsum[8];
    int i = blockIdx.x * 256 + threadIdx.x;
    int lane = threadIdx.x & 31, wp = threadIdx.x >> 5;
    int v = (i < n) ? g_cnt[i] : 0;
    int s = v;
    #pragma unroll
    for (int off = 1; off < 32; off <<= 1) {
        int u = __shfl_up_sync(0xffffffffu, s, off);
        if (lane >= off) s += u;
    }
    if (lane == 31) warpsum[wp] = s;
    __syncthreads();
    if (wp == 0 && lane < 8) {
        int ws = warpsum[lane];
        #pragma unroll
        for (int off = 1; off < 8; off <<= 1) {
            int u = __shfl_up_sync(0x000000ffu, ws, off);
            if (lane >= off) ws += u;
        }
        warpsum[lane] = ws;
    }
    __syncthreads();
    int base = (wp ? warpsum[wp - 1] : 0) + g_blkpre[blockIdx.x];
    if (i < n) {
        int pre = base + s - v;
        g_row[i] = pre;
        g_ofs[i] = pre;
        if (i == n - 1) g_row[n] = pre + v;
    }
}
__global__ void k_scatter(const int* __restrict__ ei, int Eo, int n) {
    int e = blockIdx.x * blockDim.x + threadIdx.x;
    int ET = Eo + n;
    if (e >= ET) return;
    int s, d;
    if (e < Eo) { s = ei[e]; d = ei[Eo + e]; }
    else        { s = e - Eo; d = s; }
    int pos = atomicAdd(g_ofs + d, 1);
    g_srcs[pos] = s;
}

// ---------------- layer1 feature transform + attention logits ---------------
__global__ void k_feat1(const float* __restrict__ x, const float* __restrict__ W1,
                        const float* __restrict__ a_src1, const float* __restrict__ a_dst1,
                        int n_nodes) {
    __shared__ float Ws[16 * 128];
    int c = threadIdx.x;
    for (int i = c; i < 16 * 128; i += 128) Ws[i] = W1[i];
    __syncthreads();
    int lane = c & 31, head = c >> 5;
    float as = a_src1[c], ad = a_dst1[c];
    for (int n = blockIdx.x; n < n_nodes; n += gridDim.x) {
        const float4* xr = (const float4*)(x + (size_t)n * 16);
        float4 x0 = xr[0], x1 = xr[1], x2 = xr[2], x3 = xr[3];
        float acc;
        acc  = x0.x * Ws[c];        acc += x0.y * Ws[128 + c];
        acc += x0.z * Ws[256 + c];  acc += x0.w * Ws[384 + c];
        acc += x1.x * Ws[512 + c];  acc += x1.y * Ws[640 + c];
        acc += x1.z * Ws[768 + c];  acc += x1.w * Ws[896 + c];
        acc += x2.x * Ws[1024 + c]; acc += x2.y * Ws[1152 + c];
        acc += x2.z * Ws[1280 + c]; acc += x2.w * Ws[1408 + c];
        acc += x3.x * Ws[1536 + c]; acc += x3.y * Ws[1664 + c];
        acc += x3.z * Ws[1792 + c]; acc += x3.w * Ws[1920 + c];
        g_h1h[(size_t)n * 128 + c] = __float2half_rn(acc);
        float s = acc * as, d = acc * ad;
        #pragma unroll
        for (int o = 16; o; o >>= 1) {
            s += __shfl_down_sync(0xffffffffu, s, o);
            d += __shfl_down_sync(0xffffffffu, d, o);
        }
        if (lane == 0) { g_as1[n * 4 + head] = s; g_ad1[n * 4 + head] = d; }
    }
}

// ---------------- fused layer1 gather + normalize + relu + layer2 proj ------
// one warp per dst node; lane owns channels [lane*4, lane*4+4) as 2x half2.
__device__ __forceinline__ void acc_edge(uint2 u, float w,
                                         float& ax, float& ay, float& az, float& aw) {
    __half2 a = *reinterpret_cast<__half2*>(&u.x);
    __half2 b = *reinterpret_cast<__half2*>(&u.y);
    float2 fa = __half22float2(a);
    float2 fb = __half22float2(b);
    ax = fmaf(w, fa.x, ax); ay = fmaf(w, fa.y, ay);
    az = fmaf(w, fb.x, az); aw = fmaf(w, fb.y, aw);
}

__global__ void k_gather1(const float* __restrict__ b1, const float* __restrict__ W2,
                          const float* __restrict__ a_src2, const float* __restrict__ a_dst2,
                          int n_nodes) {
    int t = blockIdx.x * blockDim.x + threadIdx.x;
    int d = t >> 5, lane = t & 31;
    if (d >= n_nodes) return;
    int head = lane >> 3;
    int c0 = lane * 4;

    float adh = g_ad1[d * 4 + head];
    float ax = 0.f, ay = 0.f, az = 0.f, aw = 0.f, den = 0.f;

    int p = g_row[d], pend = g_row[d + 1];
    for (; p + 4 <= pend; p += 4) {
        int s0 = __ldg(g_srcs + p);
        int s1 = __ldg(g_srcs + p + 1);
        int s2 = __ldg(g_srcs + p + 2);
        int s3 = __ldg(g_srcs + p + 3);
        float l0 = __ldg(g_as1 + s0 * 4 + head);
        float l1 = __ldg(g_as1 + s1 * 4 + head);
        float l2 = __ldg(g_as1 + s2 * 4 + head);
        float l3 = __ldg(g_as1 + s3 * 4 + head);
        uint2 u0 = *(const uint2*)(g_h1h + (size_t)s0 * 128 + c0);
        uint2 u1 = *(const uint2*)(g_h1h + (size_t)s1 * 128 + c0);
        uint2 u2 = *(const uint2*)(g_h1h + (size_t)s2 * 128 + c0);
        uint2 u3 = *(const uint2*)(g_h1h + (size_t)s3 * 128 + c0);
        float w0 = __expf(lrelu(l0 + adh));
        float w1 = __expf(lrelu(l1 + adh));
        float w2 = __expf(lrelu(l2 + adh));
        float w3 = __expf(lrelu(l3 + adh));
        den += (w0 + w1) + (w2 + w3);
        acc_edge(u0, w0, ax, ay, az, aw);
        acc_edge(u1, w1, ax, ay, az, aw);
        acc_edge(u2, w2, ax, ay, az, aw);
        acc_edge(u3, w3, ax, ay, az, aw);
    }
    for (; p < pend; ++p) {
        int s = __ldg(g_srcs + p);
        float w = __expf(lrelu(__ldg(g_as1 + s * 4 + head) + adh));
        den += w;
        uint2 u = *(const uint2*)(g_h1h + (size_t)s * 128 + c0);
        acc_edge(u, w, ax, ay, az, aw);
    }
    float inv = 1.f / (den + 1e-16f);
    float4 bb = *(const float4*)(b1 + c0);
    float v0 = fmaxf(ax * inv + bb.x, 0.f);
    float v1 = fmaxf(ay * inv + bb.y, 0.f);
    float v2 = fmaxf(az * inv + bb.z, 0.f);
    float v3 = fmaxf(aw * inv + bb.w, 0.f);
    float4 wA = *(const float4*)(W2 + c0 * 2);
    float4 wB = *(const float4*)(W2 + c0 * 2 + 4);
    float pq0 = v0 * wA.x + v1 * wA.z + v2 * wB.x + v3 * wB.z;
    float pq1 = v0 * wA.y + v1 * wA.w + v2 * wB.y + v3 * wB.w;
    #pragma unroll
    for (int o = 16; o; o >>= 1) {
        pq0 += __shfl_down_sync(0xffffffffu, pq0, o);
        pq1 += __shfl_down_sync(0xffffffffu, pq1, o);
    }
    if (lane == 0) {
        g_h2[d * 2] = pq0; g_h2[d * 2 + 1] = pq1;
        g_as2[d] = pq0 * a_src2[0] + pq1 * a_src2[1];
        g_ad2[d] = pq0 * a_dst2[0] + pq1 * a_dst2[1];
    }
}

// ---------------- layer2 gather -> final output -----------------------------
__global__ void k_gather2(float* __restrict__ out, const float* __restrict__ b2,
                          int n_nodes) {
    int t = blockIdx.x * blockDim.x + threadIdx.x;
    int d = t >> 5, lane = t & 31;
    if (d >= n_nodes) return;
    float add = g_ad2[d];
    float wsum = 0.f, s0 = 0.f, s1 = 0.f;
    int p0 = g_row[d], pend = g_row[d + 1];
    for (int p = p0 + lane; p < pend; p += 32) {
        int s = __ldg(g_srcs + p);
        float w = __expf(lrelu(__ldg(g_as2 + s) + add));
        wsum += w;
        float2 h = *(const float2*)(g_h2 + s * 2);
        s0 = fmaf(w, h.x, s0);
        s1 = fmaf(w, h.y, s1);
    }
    #pragma unroll
    for (int o = 16; o; o >>= 1) {
        wsum += __shfl_down_sync(0xffffffffu, wsum, o);
        s0   += __shfl_down_sync(0xffffffffu, s0, o);
        s1   += __shfl_down_sync(0xffffffffu, s1, o);
    }
    if (lane == 0) {
        float inv = 1.f / (wsum + 1e-16f);
        out[d * 2]     = s0 * inv + b2[0];
        out[d * 2 + 1] = s1 * inv + b2[1];
    }
}

extern "C" void kernel_launch(void* const* d_in, const int* in_sizes, int n_in,
                              void* d_out, int out_size) {
    const float* x   = (const float*)d_in[0];
    const int*   ei  = (const int*)d_in[1];
    const float* W1  = (const float*)d_in[2];
    const float* as1 = (const float*)d_in[3];
    const float* ad1 = (const float*)d_in[4];
    const float* b1  = (const float*)d_in[5];
    const float* W2  = (const float*)d_in[6];
    const float* as2 = (const float*)d_in[7];
    const float* ad2 = (const float*)d_in[8];
    const float* b2  = (const float*)d_in[9];
    float* out = (float*)d_out;

    int n  = in_sizes[0] / 16;   // nodes
    int Eo = in_sizes[1] / 2;    // original edges
    int ET = Eo + n;
    int nblk = (n + 255) / 256;

    // CSR build (by dst)
    k_init<<<(n + 255) / 256, 256>>>(n);
    k_hist<<<(Eo + 255) / 256, 256>>>(ei, Eo);
    k_scan1<<<nblk, 256>>>(n);
    k_scan2<<<1, 512>>>(nblk);
    k_scan3<<<nblk, 256>>>(n);
    k_scatter<<<(ET + 255) / 256, 256>>>(ei, Eo, n);

    // features
    k_feat1<<<1184, 128>>>(x, W1, as1, ad1, n);

    // fused gathers
    int warps_grid = (n * 32 + 255) / 256;
    k_gather1<<<warps_grid, 256>>>(b1, W2, as2, ad2, n);
    k_gather2<<<warps_grid, 256>>>(out, b2, n);
}

// round 6
// speedup vs baseline: 1.0207x; 1.0207x over previous
#include <cuda_runtime.h>
#include <cstdint>

#define NMAX 50000
#define EMAX 800000
#define ETMAX (EMAX + NMAX)
#define NBLK_MAX ((NMAX + 255) / 256)

// ---------------- scratch (device globals: allocation-free) ----------------
__device__ float g_h1[NMAX * 128];     // layer1 pre-act features [N,4,32]
__device__ float g_as1[NMAX * 4];      // alpha_src per (node, head)
__device__ float g_ad1[NMAX * 4];      // alpha_dst per (node, head)
__device__ float g_h2[NMAX * 2];       // layer2 features
__device__ float g_as2[NMAX];
__device__ float g_ad2[NMAX];
__device__ int   g_cnt[NMAX];          // in-degree EXCL. self loop; zeroed by k_scan3
__device__ int   g_row[NMAX + 1];      // CSR row starts (by dst)
__device__ int   g_pos[EMAX];          // per-edge within-bucket position (1-based slot)
__device__ int   g_srcs[ETMAX];        // CSR column (src) indices
__device__ int   g_blk[NBLK_MAX];      // per-block count sums
__device__ int   g_blkpre[NBLK_MAX];   // exclusive prefix of block sums

__device__ __forceinline__ float lrelu(float v) { return v > 0.f ? v : 0.2f * v; }

// ---------------- CSR build ------------------------------------------------
// histogram + per-edge bucket position; 4 edges per thread for MLP.
// PRECONDITION: g_cnt == 0 (true at module load; re-established by k_scan3).
__global__ void k_hist(const int* __restrict__ ei, int Eo) {
    int base = (blockIdx.x * blockDim.x + threadIdx.x) * 4;
    #pragma unroll
    for (int k = 0; k < 4; k++) {
        int e = base + k;
        if (e < Eo) g_pos[e] = atomicAdd(g_cnt + ei[Eo + e], 1);
    }
}
// pass 1: per-block sums of (cnt+1)
__global__ void k_scan1(int n) {
    __shared__ int sh[256];
    int i = blockIdx.x * 256 + threadIdx.x;
    sh[threadIdx.x] = (i < n) ? (g_cnt[i] + 1) : 0;
    __syncthreads();
    #pragma unroll
    for (int off = 128; off; off >>= 1) {
        if (threadIdx.x < off) sh[threadIdx.x] += sh[threadIdx.x + off];
        __syncthreads();
    }
    if (threadIdx.x == 0) g_blk[blockIdx.x] = sh[0];
}
// pass 2: single-block shuffle scan of the spine (nblk <= 512)
__global__ void k_scan2(int nblk) {
    __shared__ int warpsum[16];
    int t = threadIdx.x, lane = t & 31, wp = t >> 5;
    int v = (t < nblk) ? g_blk[t] : 0;
    int s = v;
    #pragma unroll
    for (int off = 1; off < 32; off <<= 1) {
        int u = __shfl_up_sync(0xffffffffu, s, off);
        if (lane >= off) s += u;
    }
    if (lane == 31) warpsum[wp] = s;
    __syncthreads();
    if (wp == 0) {
        int ws = (lane < 16) ? warpsum[lane] : 0;
        #pragma unroll
        for (int off = 1; off < 16; off <<= 1) {
            int u = __shfl_up_sync(0xffffffffu, ws, off);
            if (lane >= off) ws += u;
        }
        if (lane < 16) warpsum[lane] = ws;
    }
    __syncthreads();
    int base = wp ? warpsum[wp - 1] : 0;
    if (t < nblk) g_blkpre[t] = base + s - v;   // exclusive
}
// pass 3: per-block exclusive scan + spine offset -> row starts; resets cnt.
__global__ void k_scan3(int n) {
    __shared__ int warpsum[8];
    int i = blockIdx.x * 256 + threadIdx.x;
    int lane = threadIdx.x & 31, wp = threadIdx.x >> 5;
    int v = (i < n) ? (g_cnt[i] + 1) : 0;
    int s = v;
    #pragma unroll
    for (int off = 1; off < 32; off <<= 1) {
        int u = __shfl_up_sync(0xffffffffu, s, off);
        if (lane >= off) s += u;
    }
    if (lane == 31) warpsum[wp] = s;
    __syncthreads();
    if (wp == 0 && lane < 8) {
        int ws = warpsum[lane];
        #pragma unroll
        for (int off = 1; off < 8; off <<= 1) {
            int u = __shfl_up_sync(0x000000ffu, ws, off);
            if (lane >= off) ws += u;
        }
        warpsum[lane] = ws;
    }
    __syncthreads();
    int base = (wp ? warpsum[wp - 1] : 0) + g_blkpre[blockIdx.x];
    if (i < n) {
        int pre = base + s - v;
        g_row[i] = pre;
        g_cnt[i] = 0;                      // re-arm for next replay
        if (i == n - 1) g_row[n] = pre + v;
    }
}
// atomic-free scatter: slot 0 of each bucket = self loop; edges at 1+pos.
__global__ void k_scatter(const int* __restrict__ ei, int Eo, int n) {
    int base = (blockIdx.x * blockDim.x + threadIdx.x) * 4;
    #pragma unroll
    for (int k = 0; k < 4; k++) {
        int e = base + k;
        if (e < Eo) {
            int s = ei[e], d = ei[Eo + e];
            g_srcs[g_row[d] + 1 + g_pos[e]] = s;
        } else {
            int i = e - Eo;
            if (i < n) g_srcs[g_row[i]] = i;  // self loop
        }
    }
}

// ---------------- layer1 feature transform + attention logits ---------------
__global__ void k_feat1(const float* __restrict__ x, const float* __restrict__ W1,
                        const float* __restrict__ a_src1, const float* __restrict__ a_dst1,
                        int n_nodes) {
    __shared__ float Ws[16 * 128];
    int c = threadIdx.x;
    for (int i = c; i < 16 * 128; i += 128) Ws[i] = W1[i];
    __syncthreads();
    int lane = c & 31, head = c >> 5;
    float as = a_src1[c], ad = a_dst1[c];
    for (int n = blockIdx.x; n < n_nodes; n += gridDim.x) {
        const float4* xr = (const float4*)(x + (size_t)n * 16);
        float4 x0 = xr[0], x1 = xr[1], x2 = xr[2], x3 = xr[3];
        float acc;
        acc  = x0.x * Ws[c];        acc += x0.y * Ws[128 + c];
        acc += x0.z * Ws[256 + c];  acc += x0.w * Ws[384 + c];
        acc += x1.x * Ws[512 + c];  acc += x1.y * Ws[640 + c];
        acc += x1.z * Ws[768 + c];  acc += x1.w * Ws[896 + c];
        acc += x2.x * Ws[1024 + c]; acc += x2.y * Ws[1152 + c];
        acc += x2.z * Ws[1280 + c]; acc += x2.w * Ws[1408 + c];
        acc += x3.x * Ws[1536 + c]; acc += x3.y * Ws[1664 + c];
        acc += x3.z * Ws[1792 + c]; acc += x3.w * Ws[1920 + c];
        g_h1[(size_t)n * 128 + c] = acc;
        float s = acc * as, d = acc * ad;
        #pragma unroll
        for (int o = 16; o; o >>= 1) {
            s += __shfl_down_sync(0xffffffffu, s, o);
            d += __shfl_down_sync(0xffffffffu, d, o);
        }
        if (lane == 0) { g_as1[n * 4 + head] = s; g_ad1[n * 4 + head] = d; }
    }
}

// ---------------- fused layer1 gather + normalize + relu + layer2 proj ------
// one warp per dst node; lane owns channels [lane*4, lane*4+4).
__global__ void k_gather1(const float* __restrict__ b1, const float* __restrict__ W2,
                          const float* __restrict__ a_src2, const float* __restrict__ a_dst2,
                          int n_nodes) {
    int t = blockIdx.x * blockDim.x + threadIdx.x;
    int d = t >> 5, lane = t & 31;
    if (d >= n_nodes) return;
    int head = lane >> 3;
    int c0 = lane * 4;

    float adh = g_ad1[d * 4 + head];
    float ax = 0.f, ay = 0.f, az = 0.f, aw = 0.f, den = 0.f;

    int p = g_row[d], pend = g_row[d + 1];
    for (; p + 4 <= pend; p += 4) {
        int s0 = __ldg(g_srcs + p);
        int s1 = __ldg(g_srcs + p + 1);
        int s2 = __ldg(g_srcs + p + 2);
        int s3 = __ldg(g_srcs + p + 3);
        float l0 = __ldg(g_as1 + s0 * 4 + head);
        float l1 = __ldg(g_as1 + s1 * 4 + head);
        float l2 = __ldg(g_as1 + s2 * 4 + head);
        float l3 = __ldg(g_as1 + s3 * 4 + head);
        float4 h0 = *(const float4*)(g_h1 + (size_t)s0 * 128 + c0);
        float4 h1 = *(const float4*)(g_h1 + (size_t)s1 * 128 + c0);
        float4 h2 = *(const float4*)(g_h1 + (size_t)s2 * 128 + c0);
        float4 h3 = *(const float4*)(g_h1 + (size_t)s3 * 128 + c0);
        float w0 = __expf(lrelu(l0 + adh));
        float w1 = __expf(lrelu(l1 + adh));
        float w2 = __expf(lrelu(l2 + adh));
        float w3 = __expf(lrelu(l3 + adh));
        den += (w0 + w1) + (w2 + w3);
        ax = fmaf(w0, h0.x, ax); ay = fmaf(w0, h0.y, ay);
        az = fmaf(w0, h0.z, az); aw = fmaf(w0, h0.w, aw);
        ax = fmaf(w1, h1.x, ax); ay = fmaf(w1, h1.y, ay);
        az = fmaf(w1, h1.z, az); aw = fmaf(w1, h1.w, aw);
        ax = fmaf(w2, h2.x, ax); ay = fmaf(w2, h2.y, ay);
        az = fmaf(w2, h2.z, az); aw = fmaf(w2, h2.w, aw);
        ax = fmaf(w3, h3.x, ax); ay = fmaf(w3, h3.y, ay);
        az = fmaf(w3, h3.z, az); aw = fmaf(w3, h3.w, aw);
    }
    for (; p < pend; ++p) {
        int s = __ldg(g_srcs + p);
        float w = __expf(lrelu(__ldg(g_as1 + s * 4 + head) + adh));
        den += w;
        float4 h = *(const float4*)(g_h1 + (size_t)s * 128 + c0);
        ax = fmaf(w, h.x, ax); ay = fmaf(w, h.y, ay);
        az = fmaf(w, h.z, az); aw = fmaf(w, h.w, aw);
    }
    float inv = 1.f / (den + 1e-16f);
    float4 bb = *(const float4*)(b1 + c0);
    float v0 = fmaxf(ax * inv + bb.x, 0.f);
    float v1 = fmaxf(ay * inv + bb.y, 0.f);
    float v2 = fmaxf(az * inv + bb.z, 0.f);
    float v3 = fmaxf(aw * inv + bb.w, 0.f);
    float4 wA = *(const float4*)(W2 + c0 * 2);
    float4 wB = *(const float4*)(W2 + c0 * 2 + 4);
    float pq0 = v0 * wA.x + v1 * wA.z + v2 * wB.x + v3 * wB.z;
    float pq1 = v0 * wA.y + v1 * wA.w + v2 * wB.y + v3 * wB.w;
    #pragma unroll
    for (int o = 16; o; o >>= 1) {
        pq0 += __shfl_down_sync(0xffffffffu, pq0, o);
        pq1 += __shfl_down_sync(0xffffffffu, pq1, o);
    }
    if (lane == 0) {
        g_h2[d * 2] = pq0; g_h2[d * 2 + 1] = pq1;
        g_as2[d] = pq0 * a_src2[0] + pq1 * a_src2[1];
        g_ad2[d] = pq0 * a_dst2[0] + pq1 * a_dst2[1];
    }
}

// ---------------- layer2 gather -> final output -----------------------------
__global__ void k_gather2(float* __restrict__ out, const float* __restrict__ b2,
                          int n_nodes) {
    int t = blockIdx.x * blockDim.x + threadIdx.x;
    int d = t >> 5, lane = t & 31;
    if (d >= n_nodes) return;
    float add = g_ad2[d];
    float wsum = 0.f, s0 = 0.f, s1 = 0.f;
    int p0 = g_row[d], pend = g_row[d + 1];
    for (int p = p0 + lane; p < pend; p += 32) {
        int s = __ldg(g_srcs + p);
        float w = __expf(lrelu(__ldg(g_as2 + s) + add));
        wsum += w;
        float2 h = *(const float2*)(g_h2 + s * 2);
        s0 = fmaf(w, h.x, s0);
        s1 = fmaf(w, h.y, s1);
    }
    #pragma unroll
    for (int o = 16; o; o >>= 1) {
        wsum += __shfl_down_sync(0xffffffffu, wsum, o);
        s0   += __shfl_down_sync(0xffffffffu, s0, o);
        s1   += __shfl_down_sync(0xffffffffu, s1, o);
    }
    if (lane == 0) {
        float inv = 1.f / (wsum + 1e-16f);
        out[d * 2]     = s0 * inv + b2[0];
        out[d * 2 + 1] = s1 * inv + b2[1];
    }
}

extern "C" void kernel_launch(void* const* d_in, const int* in_sizes, int n_in,
                              void* d_out, int out_size) {
    const float* x   = (const float*)d_in[0];
    const int*   ei  = (const int*)d_in[1];
    const float* W1  = (const float*)d_in[2];
    const float* as1 = (const float*)d_in[3];
    const float* ad1 = (const float*)d_in[4];
    const float* b1  = (const float*)d_in[5];
    const float* W2  = (const float*)d_in[6];
    const float* as2 = (const float*)d_in[7];
    const float* ad2 = (const float*)d_in[8];
    const float* b2  = (const float*)d_in[9];
    float* out = (float*)d_out;

    int n  = in_sizes[0] / 16;   // nodes
    int Eo = in_sizes[1] / 2;    // original edges
    int ET = Eo + n;
    int nblk = (n + 255) / 256;

    // CSR build (by dst); g_cnt is zero on entry (module init / prior k_scan3)
    k_hist<<<(Eo / 4 + 255) / 256 + 1, 256>>>(ei, Eo);
    k_scan1<<<nblk, 256>>>(n);
    k_scan2<<<1, 512>>>(nblk);
    k_scan3<<<nblk, 256>>>(n);
    k_scatter<<<(ET / 4 + 255) / 256 + 1, 256>>>(ei, Eo, n);

    // features
    k_feat1<<<1184, 128>>>(x, W1, as1, ad1, n);

    // fused gathers
    int warps_grid = (n * 32 + 255) / 256;
    k_gather1<<<warps_grid, 256>>>(b1, W2, as2, ad2, n);
    k_gather2<<<warps_grid, 256>>>(out, b2, n);
}